// round 13
// baseline (speedup 1.0000x reference)
#include <cuda_runtime.h>
#include <math.h>

// Problem constants (B, C, H, W) = (2048, 1, 128, 128)
#define NB       2048
#define IMG_PIX  16384     // 128*128
#define CROP_PIX 4096      // 64*64

// Output layout: concatenation of (target, target_cut, target_scene, target_raw)
#define OFF_TARGET 0
#define OFF_CUT    (2048u * 4096u)
#define OFF_SCENE  (2u * 2048u * 4096u)
#define OFF_RAW    (OFF_SCENE + 2048u * 16384u)

struct Res4 {
    float4 tg;   // image * mask
    float4 sc;   // image * (mask==0)
};

// Mask products for one float4 at row r, fixed column group.
// csX[k] = cos*X_k and nsnX[k] = -sin*X_k are hoisted per-thread invariants.
__device__ __forceinline__ Res4 mask4_row(
    int r, float4 v,
    float sn, float cs,
    const float* __restrict__ csX, const float* __restrict__ nsnX,
    float xd, float xu, float yd, float yu)
{
    const float Y  = (float)r - 63.5f;
    const float ty = __fmul_rn(sn, Y);   // sin*Y  (xin term)
    const float cy = __fmul_rn(cs, Y);   // cos*Y  (yin term)

    float tg[4], sc[4];
    const float vv[4] = {v.x, v.y, v.z, v.w};

    #pragma unroll
    for (int k = 0; k < 4; k++) {
        // xin = cos*X + sin*Y ; yin = (-sin)*X + cos*Y  (no FMA, match reference)
        const float xin = __fadd_rn(csX[k],  ty);
        const float yin = __fadd_rn(nsnX[k], cy);
        // tcol = (xin + 63.5) + 0.5  — keep the two-add form to match reference
        const float tcol = __fadd_rn(__fadd_rn(xin, 63.5f), 0.5f);
        const float trow = __fadd_rn(__fadd_rn(yin, 63.5f), 0.5f);
        const bool m = (trow >= xd) & (trow < xu) & (tcol >= yd) & (tcol < yu);
        tg[k] = m ? vv[k] : 0.0f;
        sc[k] = m ? 0.0f  : vv[k];
    }
    Res4 o;
    o.tg = make_float4(tg[0], tg[1], tg[2], tg[3]);
    o.sc = make_float4(sc[0], sc[1], sc[2], sc[3]);
    return o;
}

__device__ __forceinline__ float4 cut4(float4 v)
{
    float4 cu;
    cu.x = fminf(__fmul_rn(v.x, 2.0f), 1.0f);
    cu.y = fminf(__fmul_rn(v.y, 2.0f), 1.0f);
    cu.z = fminf(__fmul_rn(v.z, 2.0f), 1.0f);
    cu.w = fminf(__fmul_rn(v.w, 2.0f), 1.0f);
    return cu;
}

__global__ __launch_bounds__(256)
void kd_fused_kernel(const float* __restrict__ image,
                     const float* __restrict__ azimuth,
                     const float* __restrict__ alpha,
                     float* __restrict__ out)
{
    const int b = blockIdx.x;

    const float* img   = image + (size_t)b * IMG_PIX;
    float* targ  = out + OFF_TARGET + (size_t)b * CROP_PIX;
    float* cut   = out + OFF_CUT    + (size_t)b * CROP_PIX;
    float* scene = out + OFF_SCENE  + (size_t)b * IMG_PIX;
    float* raw   = out + OFF_RAW    + (size_t)b * IMG_PIX;

    // Box bounds, replicating reference float32 arithmetic (round = half-to-even).
    float a0 = alpha[0], a1 = alpha[1], a2 = alpha[2], a3 = alpha[3];
    float xu = nearbyintf(__fadd_rn(64.0f, __fmul_rn(__fmul_rn(a0, 70.0f), 0.5f)));
    float xd = nearbyintf(__fsub_rn(64.0f, __fmul_rn(__fmul_rn(a1, 70.0f), 0.5f)));
    float yu = nearbyintf(__fadd_rn(64.0f, __fmul_rn(__fmul_rn(a2, 70.0f), 0.5f)));
    float yd = nearbyintf(__fsub_rn(64.0f, __fmul_rn(__fmul_rn(a3, 70.0f), 0.5f)));

    // masks[b] = rotate(box, -azimuth[b]); a = deg2rad(-az)
    const float ang = __fmul_rn(-azimuth[b], 0.017453292519943295f);
    float sn, cs;
    sincosf(ang, &sn, &cs);
    const float nsn = -sn;

    // Per-thread invariants: fixed column group c0 = (tid&31)*4 across all rows.
    const int s  = threadIdx.x & 31;
    const int q  = threadIdx.x >> 5;           // base row 0..7
    const int c0 = s << 2;                     // col 0,4,...,124

    float csX[4], nsnX[4];
    #pragma unroll
    for (int k = 0; k < 4; k++) {
        const float X = (float)(c0 + k) - 63.5f;
        csX[k]  = __fmul_rn(cs,  X);
        nsnX[k] = __fmul_rn(nsn, X);
    }
    const bool colOK   = (c0 >= 32) & (c0 < 96);
    const int  cropCol = (c0 - 32) >> 2;       // float4 col index in crop

    const float4* img4 = reinterpret_cast<const float4*>(img);

    // Rows rA = q+16j, rB = q+8+16j (j=0..7): 2 front-batched LDG.128/iter.
    #pragma unroll 2
    for (int j = 0; j < 8; j++) {
        const int rA = q + 16 * j;
        const int rB = rA + 8;
        const int iA = (rA << 5) + s;          // float4 index in image
        const int iB = (rB << 5) + s;

        const float4 vA = __ldcs(img4 + iA);
        const float4 vB = __ldcs(img4 + iB);

        const Res4 resA = mask4_row(rA, vA, sn, cs, csX, nsnX, xd, xu, yd, yu);
        const Res4 resB = mask4_row(rB, vB, sn, cs, csX, nsnX, xd, xu, yd, yu);

        // raw stream
        __stcs(reinterpret_cast<float4*>(raw) + iA, vA);
        __stcs(reinterpret_cast<float4*>(raw) + iB, vB);
        // scene stream
        __stcs(reinterpret_cast<float4*>(scene) + iA, resA.sc);
        __stcs(reinterpret_cast<float4*>(scene) + iB, resB.sc);

        // Central 64x64 crop [32:96]x[32:96] -> target, target_cut
        if (colOK & (rA >= 32) & (rA < 96)) {
            const int ci4 = ((rA - 32) << 4) + cropCol;
            __stcs(reinterpret_cast<float4*>(targ) + ci4, resA.tg);
            __stcs(reinterpret_cast<float4*>(cut)  + ci4, cut4(vA));
        }
        if (colOK & (rB >= 32) & (rB < 96)) {
            const int ci4 = ((rB - 32) << 4) + cropCol;
            __stcs(reinterpret_cast<float4*>(targ) + ci4, resB.tg);
            __stcs(reinterpret_cast<float4*>(cut)  + ci4, cut4(vB));
        }
    }
}

extern "C" void kernel_launch(void* const* d_in, const int* in_sizes, int n_in,
                              void* d_out, int out_size)
{
    const float* image   = (const float*)d_in[0];
    const float* azimuth = (const float*)d_in[1];
    const float* alpha   = (const float*)d_in[2];
    float* out = (float*)d_out;

    kd_fused_kernel<<<NB, 256>>>(image, azimuth, alpha, out);
}

// round 17
// speedup vs baseline: 1.0214x; 1.0214x over previous
#include <cuda_runtime.h>
#include <math.h>

// Problem constants (B, C, H, W) = (2048, 1, 128, 128)
#define NB       2048
#define IMG_PIX  16384     // 128*128
#define CROP_PIX 4096      // 64*64

// Output layout: concatenation of (target, target_cut, target_scene, target_raw)
#define OFF_TARGET 0
#define OFF_CUT    (2048u * 4096u)
#define OFF_SCENE  (2u * 2048u * 4096u)
#define OFF_RAW    (OFF_SCENE + 2048u * 16384u)

struct Res4 {
    float4 tg;   // image * mask
    float4 sc;   // image * (mask==0)
};

// Mask products for one float4 at row r; csX/nsnX are per-thread invariants
// (cos*X_k, -sin*X_k for this thread's fixed column group).
__device__ __forceinline__ Res4 mask4_row(
    int r, float4 v,
    float sn, float cs,
    const float* __restrict__ csX, const float* __restrict__ nsnX,
    float xd, float xu, float yd, float yu)
{
    const float Y  = (float)r - 63.5f;
    const float ty = __fmul_rn(sn, Y);   // sin*Y  (xin term)
    const float cy = __fmul_rn(cs, Y);   // cos*Y  (yin term)

    float tg[4], sc[4];
    const float vv[4] = {v.x, v.y, v.z, v.w};

    #pragma unroll
    for (int k = 0; k < 4; k++) {
        // xin = cos*X + sin*Y ; yin = (-sin)*X + cos*Y  (no FMA, match reference)
        const float xin = __fadd_rn(csX[k],  ty);
        const float yin = __fadd_rn(nsnX[k], cy);
        const float tcol = __fadd_rn(__fadd_rn(xin, 63.5f), 0.5f);
        const float trow = __fadd_rn(__fadd_rn(yin, 63.5f), 0.5f);
        const bool m = (trow >= xd) & (trow < xu) & (tcol >= yd) & (tcol < yu);
        tg[k] = m ? vv[k] : 0.0f;
        sc[k] = m ? 0.0f  : vv[k];
    }
    Res4 o;
    o.tg = make_float4(tg[0], tg[1], tg[2], tg[3]);
    o.sc = make_float4(sc[0], sc[1], sc[2], sc[3]);
    return o;
}

__device__ __forceinline__ float4 cut4(float4 v)
{
    float4 cu;
    cu.x = fminf(__fmul_rn(v.x, 2.0f), 1.0f);
    cu.y = fminf(__fmul_rn(v.y, 2.0f), 1.0f);
    cu.z = fminf(__fmul_rn(v.z, 2.0f), 1.0f);
    cu.w = fminf(__fmul_rn(v.w, 2.0f), 1.0f);
    return cu;
}

__global__ __launch_bounds__(256)
void kd_fused_kernel(const float* __restrict__ image,
                     const float* __restrict__ azimuth,
                     const float* __restrict__ alpha,
                     float* __restrict__ out)
{
    const int b = blockIdx.x;

    const float* img   = image + (size_t)b * IMG_PIX;
    float* targ  = out + OFF_TARGET + (size_t)b * CROP_PIX;
    float* cut   = out + OFF_CUT    + (size_t)b * CROP_PIX;
    float* scene = out + OFF_SCENE  + (size_t)b * IMG_PIX;
    float* raw   = out + OFF_RAW    + (size_t)b * IMG_PIX;

    // Box bounds, replicating reference float32 arithmetic (round = half-to-even).
    float a0 = alpha[0], a1 = alpha[1], a2 = alpha[2], a3 = alpha[3];
    float xu = nearbyintf(__fadd_rn(64.0f, __fmul_rn(__fmul_rn(a0, 70.0f), 0.5f)));
    float xd = nearbyintf(__fsub_rn(64.0f, __fmul_rn(__fmul_rn(a1, 70.0f), 0.5f)));
    float yu = nearbyintf(__fadd_rn(64.0f, __fmul_rn(__fmul_rn(a2, 70.0f), 0.5f)));
    float yd = nearbyintf(__fsub_rn(64.0f, __fmul_rn(__fmul_rn(a3, 70.0f), 0.5f)));

    // masks[b] = rotate(box, -azimuth[b]); a = deg2rad(-az)
    const float ang = __fmul_rn(-azimuth[b], 0.017453292519943295f);
    float sn, cs;
    sincosf(ang, &sn, &cs);
    const float nsn = -sn;

    // Per-thread invariants: fixed column group c0 = (tid&31)*4 across all rows
    // (R5 iteration layout: i = tid + 256*step keeps tid&31 constant).
    const int s  = threadIdx.x & 31;
    const int c0 = s << 2;                     // col 0,4,...,124

    float csX[4], nsnX[4];
    #pragma unroll
    for (int k = 0; k < 4; k++) {
        const float X = (float)(c0 + k) - 63.5f;
        csX[k]  = __fmul_rn(cs,  X);
        nsnX[k] = __fmul_rn(nsn, X);
    }
    const bool colOK   = (c0 >= 32) & (c0 < 96);
    const int  cropCol = (c0 - 32) >> 2;       // float4 col index in crop row

    const float4* img4 = reinterpret_cast<const float4*>(img);

    // R5 structure: 2 front-batched LDG.128 per iteration (i, i+256),
    // stores grouped per output stream.
    #pragma unroll 2
    for (int j = 0; j < 8; j++) {
        const int iA = threadIdx.x + j * 512;
        const int iB = iA + 256;
        const int rA = iA >> 5;                // row 0..127
        const int rB = iB >> 5;

        const float4 vA = __ldcs(img4 + iA);
        const float4 vB = __ldcs(img4 + iB);

        const Res4 resA = mask4_row(rA, vA, sn, cs, csX, nsnX, xd, xu, yd, yu);
        const Res4 resB = mask4_row(rB, vB, sn, cs, csX, nsnX, xd, xu, yd, yu);

        // raw stream (both halves back-to-back)
        __stcs(reinterpret_cast<float4*>(raw) + iA, vA);
        __stcs(reinterpret_cast<float4*>(raw) + iB, vB);
        // scene stream
        __stcs(reinterpret_cast<float4*>(scene) + iA, resA.sc);
        __stcs(reinterpret_cast<float4*>(scene) + iB, resB.sc);

        // Central 64x64 crop [32:96]x[32:96] -> target, target_cut
        if (colOK & (rA >= 32) & (rA < 96)) {
            const int ci4 = ((rA - 32) << 4) + cropCol;
            __stcs(reinterpret_cast<float4*>(targ) + ci4, resA.tg);
            __stcs(reinterpret_cast<float4*>(cut)  + ci4, cut4(vA));
        }
        if (colOK & (rB >= 32) & (rB < 96)) {
            const int ci4 = ((rB - 32) << 4) + cropCol;
            __stcs(reinterpret_cast<float4*>(targ) + ci4, resB.tg);
            __stcs(reinterpret_cast<float4*>(cut)  + ci4, cut4(vB));
        }
    }
}

extern "C" void kernel_launch(void* const* d_in, const int* in_sizes, int n_in,
                              void* d_out, int out_size)
{
    const float* image   = (const float*)d_in[0];
    const float* azimuth = (const float*)d_in[1];
    const float* alpha   = (const float*)d_in[2];
    float* out = (float*)d_out;

    kd_fused_kernel<<<NB, 256>>>(image, azimuth, alpha, out);
}